// round 6
// baseline (speedup 1.0000x reference)
#include <cuda_runtime.h>
#include <math.h>
#include <stdint.h>

#define NINT 37449
#define NVOC 32000

// ---------------- device scratch (no allocs allowed) ----------------
static __device__ float  g_Pb[(size_t)NVOC * 128]; // emb@W_in + b_in
static __device__ float  g_T [(size_t)NVOC * 128]; // tanh(Pb)
static __device__ float  g_Q [(size_t)NVOC * 128]; // T@W_out
static __device__ float  g_h [(size_t)NINT * 128]; // hidden, internal nodes
static __device__ float2 g_Bfrag[3][8192];         // {Win,U,Wout} mma-fragment images

// smem: As [128][132] floats (B frags read from global via L1)
#define AS_BYTES   (128 * 132 * 4)   // 67584
#define SMEM_BYTES AS_BYTES

__device__ __forceinline__ void split(float v, uint32_t& hi, uint32_t& lo) {
    uint32_t u = __float_as_uint(v) & 0xffffe000u;
    hi = u;
    lo = __float_as_uint(v - __uint_as_float(u));
}

__device__ __forceinline__ void mma8(float d[4], const uint32_t a[4],
                                     uint32_t b0, uint32_t b1) {
    asm volatile(
        "mma.sync.aligned.m16n8k8.row.col.f32.tf32.tf32.f32 "
        "{%0,%1,%2,%3}, {%4,%5,%6,%7}, {%8,%9}, {%0,%1,%2,%3};"
        : "+f"(d[0]), "+f"(d[1]), "+f"(d[2]), "+f"(d[3])
        : "r"(a[0]), "r"(a[1]), "r"(a[2]), "r"(a[3]), "r"(b0), "r"(b1));
}

// 128x128x128 tile GEMM, tf32 x3. Warp (wr,wc): rows wr*32..+32, cols wc*64..+64.
__device__ __forceinline__ void gemm_core(const float* __restrict__ As,
                                          const float2* __restrict__ Bf,
                                          int wr, int wc, int lane,
                                          float acc[2][8][4])
{
    const int rA = wr * 32 + (lane >> 2);
    const int cA = lane & 3;
#pragma unroll 2
    for (int ks = 0; ks < 16; ks++) {
        uint32_t ahi[2][4], alo[2][4];
#pragma unroll
        for (int mt = 0; mt < 2; mt++) {
            const int r = rA + mt * 16;
            const int c = ks * 8 + cA;
            split(As[r * 132 + c],           ahi[mt][0], alo[mt][0]);
            split(As[(r + 8) * 132 + c],     ahi[mt][1], alo[mt][1]);
            split(As[r * 132 + c + 4],       ahi[mt][2], alo[mt][2]);
            split(As[(r + 8) * 132 + c + 4], ahi[mt][3], alo[mt][3]);
        }
#pragma unroll
        for (int nt = 0; nt < 8; nt++) {
            float2 b = __ldg(&Bf[(ks * 16 + wc * 8 + nt) * 32 + lane]);
            uint32_t bh0, bl0, bh1, bl1;
            split(b.x, bh0, bl0);
            split(b.y, bh1, bl1);
#pragma unroll
            for (int mt = 0; mt < 2; mt++) {
                mma8(acc[mt][nt], ahi[mt], bh0, bh1);
                mma8(acc[mt][nt], ahi[mt], bl0, bl1);
                mma8(acc[mt][nt], alo[mt], bh0, bh1);
            }
        }
    }
}

#define ACC_ZERO(acc) do { \
    _Pragma("unroll") for (int _a = 0; _a < 2; _a++) \
    _Pragma("unroll") for (int _b = 0; _b < 8; _b++) \
    _Pragma("unroll") for (int _c = 0; _c < 4; _c++) acc[_a][_b][_c] = 0.f; } while (0)

// ---------------------------------------------------------------------------
// k_prep: mma-fragment images of the 3 weights (B[n][k] = W[k][n]).
// ---------------------------------------------------------------------------
__global__ void k_prep(const float* __restrict__ Win, const float* __restrict__ U,
                       const float* __restrict__ Wout)
{
    int i = blockIdx.x * 256 + threadIdx.x;
    if (i < 3 * 8192) {
        int w = i >> 13, r = i & 8191;
        int ks = r >> 9, ntg = (r >> 5) & 15, lane = r & 31;
        int n = ntg * 8 + (lane >> 2);
        int k0 = ks * 8 + (lane & 3);
        const float* W = (w == 0) ? Win : ((w == 1) ? U : Wout);
        g_Bfrag[w][r] = make_float2(W[k0 * 128 + n], W[(k0 + 4) * 128 + n]);
    }
}

// ---------------------------------------------------------------------------
// k_vocab: Pb = emb@W_in + b_in; T = tanh(Pb); Q = T@W_out  (128 rows/block)
// RACE-FIXED: sync before restaging As between the two GEMM passes.
// ---------------------------------------------------------------------------
__global__ void __launch_bounds__(256, 2)
k_vocab(const float* __restrict__ emb, const float* __restrict__ b_in)
{
    extern __shared__ char sm[];
    float* As = (float*)sm;

    const int tid = threadIdx.x, wid = tid >> 5, lane = tid & 31;
    const int wr = wid & 3, wc = wid >> 2;
    const int row0 = blockIdx.x * 128;

    for (int i = tid; i < 4096; i += 256) {
        int row = i >> 5, q = i & 31;
        float4 v = ((const float4*)emb)[(size_t)(row0 + row) * 32 + q];
        *(float4*)&As[row * 132 + q * 4] = v;
    }
    __syncthreads();

    float acc[2][8][4];
    ACC_ZERO(acc);
    gemm_core(As, g_Bfrag[0], wr, wc, lane, acc);

    // epilogue 1: compute Pb/T, write them, keep tanh in acc
#pragma unroll
    for (int mt = 0; mt < 2; mt++)
#pragma unroll
        for (int h = 0; h < 2; h++) {
            const size_t node = row0 + wr * 32 + mt * 16 + (lane >> 2) + h * 8;
#pragma unroll
            for (int nt = 0; nt < 8; nt++) {
                const int col = wc * 64 + nt * 8 + (lane & 3) * 2;
                float2 b = *(const float2*)&b_in[col];
                float p0 = acc[mt][nt][h * 2]     + b.x;
                float p1 = acc[mt][nt][h * 2 + 1] + b.y;
                *(float2*)&g_Pb[node * 128 + col] = make_float2(p0, p1);
                float t0 = tanhf(p0), t1 = tanhf(p1);
                *(float2*)&g_T[node * 128 + col] = make_float2(t0, t1);
                acc[mt][nt][h * 2]     = t0;
                acc[mt][nt][h * 2 + 1] = t1;
            }
        }
    __syncthreads();   // ALL warps done READING As in pass 1
#pragma unroll
    for (int mt = 0; mt < 2; mt++)
#pragma unroll
        for (int h = 0; h < 2; h++) {
            const int r = wr * 32 + mt * 16 + (lane >> 2) + h * 8;
#pragma unroll
            for (int nt = 0; nt < 8; nt++) {
                const int col = wc * 64 + nt * 8 + (lane & 3) * 2;
                As[r * 132 + col]     = acc[mt][nt][h * 2];
                As[r * 132 + col + 1] = acc[mt][nt][h * 2 + 1];
            }
        }
    __syncthreads();   // restage visible to all

    ACC_ZERO(acc);
    gemm_core(As, g_Bfrag[2], wr, wc, lane, acc);

#pragma unroll
    for (int mt = 0; mt < 2; mt++)
#pragma unroll
        for (int h = 0; h < 2; h++) {
            const size_t node = row0 + wr * 32 + mt * 16 + (lane >> 2) + h * 8;
#pragma unroll
            for (int nt = 0; nt < 8; nt++) {
                const int col = wc * 64 + nt * 8 + (lane & 3) * 2;
                *(float2*)&g_Q[node * 128 + col] =
                    make_float2(acc[mt][nt][h * 2], acc[mt][nt][h * 2 + 1]);
            }
        }
}

// ---------------------------------------------------------------------------
// k_level5f: h = tanh(Pb[x*m]*m + (sum_c m_c*T[x_c]) @ U), then FUSED
//            out[node] = h @ W_out + b_out  (rows 4681..37449)
// ---------------------------------------------------------------------------
__global__ void __launch_bounds__(256, 2)
k_level5f(int s, const int* __restrict__ x, const int* __restrict__ mask,
          const int* __restrict__ children, const float* __restrict__ b_out,
          float* __restrict__ out)
{
    extern __shared__ char sm[];
    float* As = (float*)sm;

    const int tid = threadIdx.x, wid = tid >> 5, lane = tid & 31;
    const int wr = wid & 3, wc = wid >> 2;
    const int row0 = blockIdx.x * 128;

    for (int i = tid; i < 4096; i += 256) {
        int row = i >> 5, f4 = i & 31;
        int node = s + row0 + row;
        float4 acc4 = make_float4(0.f, 0.f, 0.f, 0.f);
#pragma unroll
        for (int c = 0; c < 8; c++) {
            int cc = children[(size_t)node * 8 + c];
            int mm = mask[cc];
            float fm = (float)mm;
            float4 t = ((const float4*)g_T)[(size_t)(x[cc] * mm) * 32 + f4];
            acc4.x = fmaf(t.x, fm, acc4.x); acc4.y = fmaf(t.y, fm, acc4.y);
            acc4.z = fmaf(t.z, fm, acc4.z); acc4.w = fmaf(t.w, fm, acc4.w);
        }
        *(float4*)&As[row * 132 + f4 * 4] = acc4;
    }
    __syncthreads();

    float acc[2][8][4];
    ACC_ZERO(acc);
    gemm_core(As, g_Bfrag[1], wr, wc, lane, acc);

    // epilogue 1: h = tanh(acc + Pb*m); write g_h; keep h in acc
#pragma unroll
    for (int mt = 0; mt < 2; mt++)
#pragma unroll
        for (int h = 0; h < 2; h++) {
            const int node = s + row0 + wr * 32 + mt * 16 + (lane >> 2) + h * 8;
            const float mf = (float)mask[node];
            const size_t xm = (size_t)(x[node] * mask[node]);
#pragma unroll
            for (int nt = 0; nt < 8; nt++) {
                const int col = wc * 64 + nt * 8 + (lane & 3) * 2;
                float2 p = *(const float2*)&g_Pb[xm * 128 + col];
                float o0 = tanhf(acc[mt][nt][h * 2]     + p.x * mf);
                float o1 = tanhf(acc[mt][nt][h * 2 + 1] + p.y * mf);
                *(float2*)&g_h[(size_t)node * 128 + col] = make_float2(o0, o1);
                acc[mt][nt][h * 2]     = o0;
                acc[mt][nt][h * 2 + 1] = o1;
            }
        }
    __syncthreads();   // all warps done reading As in pass 1
#pragma unroll
    for (int mt = 0; mt < 2; mt++)
#pragma unroll
        for (int h = 0; h < 2; h++) {
            const int r = wr * 32 + mt * 16 + (lane >> 2) + h * 8;
#pragma unroll
            for (int nt = 0; nt < 8; nt++) {
                const int col = wc * 64 + nt * 8 + (lane & 3) * 2;
                As[r * 132 + col]     = acc[mt][nt][h * 2];
                As[r * 132 + col + 1] = acc[mt][nt][h * 2 + 1];
            }
        }
    __syncthreads();

    // pass 2: out = h @ W_out + b_out
    ACC_ZERO(acc);
    gemm_core(As, g_Bfrag[2], wr, wc, lane, acc);

#pragma unroll
    for (int mt = 0; mt < 2; mt++)
#pragma unroll
        for (int h = 0; h < 2; h++) {
            const int node = s + row0 + wr * 32 + mt * 16 + (lane >> 2) + h * 8;
#pragma unroll
            for (int nt = 0; nt < 8; nt++) {
                const int col = wc * 64 + nt * 8 + (lane & 3) * 2;
                float2 b = *(const float2*)&b_out[col];
                *(float2*)&out[(size_t)node * 128 + col] =
                    make_float2(acc[mt][nt][h * 2] + b.x,
                                acc[mt][nt][h * 2 + 1] + b.y);
            }
        }
}

// ---------------------------------------------------------------------------
// node-level FFMA body: 16 nodes per block-slot, 256 threads
// ---------------------------------------------------------------------------
__device__ __forceinline__ void nodes_body(int base, int s, int e,
                                           const int* __restrict__ x,
                                           const int* __restrict__ mask,
                                           const int* __restrict__ children,
                                           const float* __restrict__ U,
                                           float (*agg)[128])
{
    const int tid = threadIdx.x;
    const int col = tid & 127, half = tid >> 7;

#pragma unroll
    for (int g = 0; g < 8; g++) {
        const int node = base + half * 8 + g;
        const int nb = (node < e) ? node : s;
        float sum = 0.f;
#pragma unroll
        for (int c = 0; c < 8; c++)
            sum += g_h[(size_t)children[(size_t)nb * 8 + c] * 128 + col];
        agg[half * 8 + g][col] = sum;
    }
    __syncthreads();

    float acc[8];
#pragma unroll
    for (int g = 0; g < 8; g++) acc[g] = 0.f;
#pragma unroll 4
    for (int k = 0; k < 128; k++) {
        const float u = __ldg(&U[k * 128 + col]);
#pragma unroll
        for (int g = 0; g < 8; g++)
            acc[g] = fmaf(agg[half * 8 + g][k], u, acc[g]);
    }

#pragma unroll
    for (int g = 0; g < 8; g++) {
        const int node = base + half * 8 + g;
        if (node < e) {
            const float mf = (float)mask[node];
            const int xm = x[node] * mask[node];
            const float hin = g_Pb[(size_t)xm * 128 + col] * mf;
            g_h[(size_t)node * 128 + col] = tanhf(hin + acc[g]);
        }
    }
}

// ---------------------------------------------------------------------------
// k_mix4: blocks [0,256) = level-4 node blocks; blocks [256,2304) = leaf output
// ---------------------------------------------------------------------------
__global__ void __launch_bounds__(256, 4)
k_mix4(const int* __restrict__ x, const int* __restrict__ mask,
       const int* __restrict__ children, const float* __restrict__ U,
       const float* __restrict__ b_out, float* __restrict__ out)
{
    __shared__ float agg[16][128];
    if (blockIdx.x < 256) {
        const int s = 585, e = 4681;
        nodes_body(s + blockIdx.x * 16, s, e, x, mask, children, U, agg);
    } else {
        const int bid = blockIdx.x - 256;            // 0..2047
        const float4 bv = ((const float4*)b_out)[threadIdx.x & 31];
        int idx = bid * 256 + threadIdx.x;           // stride 2048*256
#pragma unroll 4
        for (int it = 0; it < 16; it++, idx += 2048 * 256) {
            const int rr = idx >> 5, c = idx & 31;
            const int node = NINT + rr;
            const int m = mask[node];
            const int xm = x[node] * m;
            const float mf = (float)m;
            float4 q = ((const float4*)g_Q)[(size_t)xm * 32 + c];
            float4 o = make_float4(fmaf(q.x, mf, bv.x), fmaf(q.y, mf, bv.y),
                                   fmaf(q.z, mf, bv.z), fmaf(q.w, mf, bv.w));
            ((float4*)out)[(size_t)node * 32 + c] = o;
        }
    }
}

// ---------------------------------------------------------------------------
// k_nodes: standalone node-level kernel (L3)
// ---------------------------------------------------------------------------
__global__ void __launch_bounds__(256, 4)
k_nodes(int s, int n, const int* __restrict__ x, const int* __restrict__ mask,
        const int* __restrict__ children, const float* __restrict__ U)
{
    __shared__ float agg[16][128];
    nodes_body(s + blockIdx.x * 16, s, s + n, x, mask, children, U, agg);
}

// ---------------------------------------------------------------------------
// k_tail: levels 2,1,0 (64+8+1 nodes) in ONE block
// ---------------------------------------------------------------------------
__global__ void __launch_bounds__(256, 1)
k_tail(const int* __restrict__ x, const int* __restrict__ mask,
       const int* __restrict__ children, const float* __restrict__ U)
{
    __shared__ float agg[16][128];
    const int ls[3] = {9, 1, 0};
    const int ln[3] = {64, 8, 1};
    for (int lv = 0; lv < 3; lv++) {
        const int s = ls[lv], e = s + ln[lv];
        for (int base = s; base < e; base += 16) {
            nodes_body(base, s, e, x, mask, children, U, agg);
            __syncthreads();
        }
    }
}

// ---------------------------------------------------------------------------
// k_out_t: out[r0 .. r0+nrows) = g_h @ W_out + b_out  (tensor path)
// ---------------------------------------------------------------------------
__global__ void __launch_bounds__(256, 2)
k_out_t(int r0, int nrows, const float* __restrict__ b_out, float* __restrict__ out)
{
    extern __shared__ char sm[];
    float* As = (float*)sm;

    const int tid = threadIdx.x, wid = tid >> 5, lane = tid & 31;
    const int wr = wid & 3, wc = wid >> 2;
    const int row0 = r0 + blockIdx.x * 128;
    const int e = r0 + nrows;

    for (int i = tid; i < 4096; i += 256) {
        int row = i >> 5, q = i & 31;
        int rr = row0 + row; if (rr >= e) rr = e - 1;
        float4 v = ((const float4*)g_h)[(size_t)rr * 32 + q];
        *(float4*)&As[row * 132 + q * 4] = v;
    }
    __syncthreads();

    float acc[2][8][4];
    ACC_ZERO(acc);
    gemm_core(As, g_Bfrag[2], wr, wc, lane, acc);

#pragma unroll
    for (int mt = 0; mt < 2; mt++)
#pragma unroll
        for (int h = 0; h < 2; h++) {
            const int node = row0 + wr * 32 + mt * 16 + (lane >> 2) + h * 8;
            if (node < e) {
#pragma unroll
                for (int nt = 0; nt < 8; nt++) {
                    const int col = wc * 64 + nt * 8 + (lane & 3) * 2;
                    float2 b = *(const float2*)&b_out[col];
                    *(float2*)&out[(size_t)node * 128 + col] =
                        make_float2(acc[mt][nt][h * 2] + b.x,
                                    acc[mt][nt][h * 2 + 1] + b.y);
                }
            }
        }
}

// ---------------------------------------------------------------------------
extern "C" void kernel_launch(void* const* d_in, const int* in_sizes, int n_in,
                              void* d_out, int out_size)
{
    const int*   x        = (const int*)  d_in[0];
    const int*   mask     = (const int*)  d_in[1];
    const int*   children = (const int*)  d_in[2];
    const float* emb      = (const float*)d_in[3];
    const float* W_in     = (const float*)d_in[4];
    const float* b_in     = (const float*)d_in[5];
    const float* U        = (const float*)d_in[6];
    const float* W_out    = (const float*)d_in[7];
    const float* b_out    = (const float*)d_in[8];
    float*       out      = (float*)d_out;
    (void)in_sizes; (void)n_in; (void)out_size;

    cudaFuncSetAttribute(k_vocab,   cudaFuncAttributeMaxDynamicSharedMemorySize, SMEM_BYTES);
    cudaFuncSetAttribute(k_level5f, cudaFuncAttributeMaxDynamicSharedMemorySize, SMEM_BYTES);
    cudaFuncSetAttribute(k_out_t,   cudaFuncAttributeMaxDynamicSharedMemorySize, SMEM_BYTES);

    k_prep<<<96, 256>>>(W_in, U, W_out);
    k_vocab<<<250, 256, SMEM_BYTES>>>(emb, b_in);

    // L5 hidden + fused out rows 4681..37449
    k_level5f<<<256, 256, SMEM_BYTES>>>(4681, x, mask, children, b_out, out);

    // L4 node blocks + all leaf outputs in one launch
    k_mix4<<<2304, 256>>>(x, mask, children, U, b_out, out);

    k_nodes<<<32, 256>>>(73, 512, x, mask, children, U);  // L3
    k_tail<<<1, 256>>>(x, mask, children, U);             // L2..L0

    // out rows 0..4681
    k_out_t<<<37, 256, SMEM_BYTES>>>(0, 4681, b_out, out);
}

// round 7
// speedup vs baseline: 1.0880x; 1.0880x over previous
#include <cuda_runtime.h>
#include <math.h>
#include <stdint.h>

#define NINT 37449
#define NVOC 32000

// ---------------- device scratch (no allocs allowed) ----------------
static __device__ float  g_Pb[(size_t)NVOC * 128]; // emb@W_in + b_in
static __device__ float  g_T [(size_t)NVOC * 128]; // tanh(Pb)
static __device__ float  g_Q [(size_t)NVOC * 128]; // T@W_out
static __device__ float  g_h [(size_t)NINT * 128]; // hidden, internal nodes
static __device__ float4 g_Bfrag[3][8192];         // {Win,U,Wout} frags: {hi0,hi1,lo0,lo1}

// smem: As [128][132] floats
#define AS_BYTES   (128 * 132 * 4)   // 67584
#define SMEM_BYTES AS_BYTES

__device__ __forceinline__ void split(float v, uint32_t& hi, uint32_t& lo) {
    uint32_t u = __float_as_uint(v) & 0xffffe000u;
    hi = u;
    lo = __float_as_uint(v - __uint_as_float(u));
}
__device__ __forceinline__ float hi13(float v) {
    return __uint_as_float(__float_as_uint(v) & 0xffffe000u);
}

__device__ __forceinline__ void mma8(float d[4], const uint32_t a[4],
                                     uint32_t b0, uint32_t b1) {
    asm volatile(
        "mma.sync.aligned.m16n8k8.row.col.f32.tf32.tf32.f32 "
        "{%0,%1,%2,%3}, {%4,%5,%6,%7}, {%8,%9}, {%0,%1,%2,%3};"
        : "+f"(d[0]), "+f"(d[1]), "+f"(d[2]), "+f"(d[3])
        : "r"(a[0]), "r"(a[1]), "r"(a[2]), "r"(a[3]), "r"(b0), "r"(b1));
}

// 128x128x128 tile GEMM, tf32 x3, B pre-split in g_Bfrag.
// Warp (wr,wc): rows wr*32..+32, cols wc*64..+64.
__device__ __forceinline__ void gemm_core(const float* __restrict__ As,
                                          const float4* __restrict__ Bf,
                                          int wr, int wc, int lane,
                                          float acc[2][8][4])
{
    const int rA = wr * 32 + (lane >> 2);
    const int cA = lane & 3;
#pragma unroll 2
    for (int ks = 0; ks < 16; ks++) {
        uint32_t ahi[2][4], alo[2][4];
#pragma unroll
        for (int mt = 0; mt < 2; mt++) {
            const int r = rA + mt * 16;
            const int c = ks * 8 + cA;
            split(As[r * 132 + c],           ahi[mt][0], alo[mt][0]);
            split(As[(r + 8) * 132 + c],     ahi[mt][1], alo[mt][1]);
            split(As[r * 132 + c + 4],       ahi[mt][2], alo[mt][2]);
            split(As[(r + 8) * 132 + c + 4], ahi[mt][3], alo[mt][3]);
        }
#pragma unroll
        for (int nt = 0; nt < 8; nt++) {
            float4 b = __ldg(&Bf[(ks * 16 + wc * 8 + nt) * 32 + lane]);
            const uint32_t bh0 = __float_as_uint(b.x), bh1 = __float_as_uint(b.y);
            const uint32_t bl0 = __float_as_uint(b.z), bl1 = __float_as_uint(b.w);
#pragma unroll
            for (int mt = 0; mt < 2; mt++) {
                mma8(acc[mt][nt], ahi[mt], bh0, bh1);
                mma8(acc[mt][nt], ahi[mt], bl0, bl1);
                mma8(acc[mt][nt], alo[mt], bh0, bh1);
            }
        }
    }
}

#define ACC_ZERO(acc) do { \
    _Pragma("unroll") for (int _a = 0; _a < 2; _a++) \
    _Pragma("unroll") for (int _b = 0; _b < 8; _b++) \
    _Pragma("unroll") for (int _c = 0; _c < 4; _c++) acc[_a][_b][_c] = 0.f; } while (0)

// ---------------------------------------------------------------------------
// k_prep: pre-split mma-fragment images (B[n][k] = W[k][n]).
// [w][ks*512 + ntg*32 + lane] = {hi(W[k0][n]), hi(W[k0+4][n]), lo0, lo1}
// ---------------------------------------------------------------------------
__global__ void k_prep(const float* __restrict__ Win, const float* __restrict__ U,
                       const float* __restrict__ Wout)
{
    int i = blockIdx.x * 256 + threadIdx.x;
    if (i < 3 * 8192) {
        int w = i >> 13, r = i & 8191;
        int ks = r >> 9, ntg = (r >> 5) & 15, lane = r & 31;
        int n = ntg * 8 + (lane >> 2);
        int k0 = ks * 8 + (lane & 3);
        const float* W = (w == 0) ? Win : ((w == 1) ? U : Wout);
        float v0 = W[k0 * 128 + n], v1 = W[(k0 + 4) * 128 + n];
        float h0 = hi13(v0), h1 = hi13(v1);
        g_Bfrag[w][r] = make_float4(h0, h1, v0 - h0, v1 - h1);
    }
}

// ---------------------------------------------------------------------------
// k_vocab: Pb = emb@W_in + b_in; T = tanh(Pb); Q = T@W_out  (128 rows/block)
// ---------------------------------------------------------------------------
__global__ void __launch_bounds__(256, 2)
k_vocab(const float* __restrict__ emb, const float* __restrict__ b_in)
{
    extern __shared__ char sm[];
    float* As = (float*)sm;

    const int tid = threadIdx.x, wid = tid >> 5, lane = tid & 31;
    const int wr = wid & 3, wc = wid >> 2;
    const int row0 = blockIdx.x * 128;

    for (int i = tid; i < 4096; i += 256) {
        int row = i >> 5, q = i & 31;
        float4 v = ((const float4*)emb)[(size_t)(row0 + row) * 32 + q];
        *(float4*)&As[row * 132 + q * 4] = v;
    }
    __syncthreads();

    float acc[2][8][4];
    ACC_ZERO(acc);
    gemm_core(As, g_Bfrag[0], wr, wc, lane, acc);

    // epilogue 1: Pb, T; keep tanh in acc
#pragma unroll
    for (int mt = 0; mt < 2; mt++)
#pragma unroll
        for (int h = 0; h < 2; h++) {
            const size_t node = row0 + wr * 32 + mt * 16 + (lane >> 2) + h * 8;
#pragma unroll
            for (int nt = 0; nt < 8; nt++) {
                const int col = wc * 64 + nt * 8 + (lane & 3) * 2;
                float2 b = *(const float2*)&b_in[col];
                float p0 = acc[mt][nt][h * 2]     + b.x;
                float p1 = acc[mt][nt][h * 2 + 1] + b.y;
                *(float2*)&g_Pb[node * 128 + col] = make_float2(p0, p1);
                float t0 = tanhf(p0), t1 = tanhf(p1);
                *(float2*)&g_T[node * 128 + col] = make_float2(t0, t1);
                acc[mt][nt][h * 2]     = t0;
                acc[mt][nt][h * 2 + 1] = t1;
            }
        }
    __syncthreads();   // all warps done READING As in pass 1
#pragma unroll
    for (int mt = 0; mt < 2; mt++)
#pragma unroll
        for (int h = 0; h < 2; h++) {
            const int r = wr * 32 + mt * 16 + (lane >> 2) + h * 8;
#pragma unroll
            for (int nt = 0; nt < 8; nt++) {
                const int col = wc * 64 + nt * 8 + (lane & 3) * 2;
                As[r * 132 + col]     = acc[mt][nt][h * 2];
                As[r * 132 + col + 1] = acc[mt][nt][h * 2 + 1];
            }
        }
    __syncthreads();

    ACC_ZERO(acc);
    gemm_core(As, g_Bfrag[2], wr, wc, lane, acc);

#pragma unroll
    for (int mt = 0; mt < 2; mt++)
#pragma unroll
        for (int h = 0; h < 2; h++) {
            const size_t node = row0 + wr * 32 + mt * 16 + (lane >> 2) + h * 8;
#pragma unroll
            for (int nt = 0; nt < 8; nt++) {
                const int col = wc * 64 + nt * 8 + (lane & 3) * 2;
                *(float2*)&g_Q[node * 128 + col] =
                    make_float2(acc[mt][nt][h * 2], acc[mt][nt][h * 2 + 1]);
            }
        }
}

// ---------------------------------------------------------------------------
// k_level5f: h = tanh(Pb[x*m]*m + (sum_c m_c*T[x_c]) @ U), then fused
//            out[node] = h @ W_out + b_out  (rows 4681..37449)
// ---------------------------------------------------------------------------
__global__ void __launch_bounds__(256, 2)
k_level5f(int s, const int* __restrict__ x, const int* __restrict__ mask,
          const int* __restrict__ children, const float* __restrict__ b_out,
          float* __restrict__ out)
{
    extern __shared__ char sm[];
    float* As = (float*)sm;

    const int tid = threadIdx.x, wid = tid >> 5, lane = tid & 31;
    const int wr = wid & 3, wc = wid >> 2;
    const int row0 = blockIdx.x * 128;

    for (int i = tid; i < 4096; i += 256) {
        int row = i >> 5, f4 = i & 31;
        int node = s + row0 + row;
        float4 acc4 = make_float4(0.f, 0.f, 0.f, 0.f);
#pragma unroll
        for (int c = 0; c < 8; c++) {
            int cc = children[(size_t)node * 8 + c];
            int mm = mask[cc];
            float fm = (float)mm;
            float4 t = ((const float4*)g_T)[(size_t)(x[cc] * mm) * 32 + f4];
            acc4.x = fmaf(t.x, fm, acc4.x); acc4.y = fmaf(t.y, fm, acc4.y);
            acc4.z = fmaf(t.z, fm, acc4.z); acc4.w = fmaf(t.w, fm, acc4.w);
        }
        *(float4*)&As[row * 132 + f4 * 4] = acc4;
    }
    __syncthreads();

    float acc[2][8][4];
    ACC_ZERO(acc);
    gemm_core(As, g_Bfrag[1], wr, wc, lane, acc);

    // epilogue 1: h = tanh(acc + Pb*m); write g_h; keep h in acc
#pragma unroll
    for (int mt = 0; mt < 2; mt++)
#pragma unroll
        for (int h = 0; h < 2; h++) {
            const int node = s + row0 + wr * 32 + mt * 16 + (lane >> 2) + h * 8;
            const float mf = (float)mask[node];
            const size_t xm = (size_t)(x[node] * mask[node]);
#pragma unroll
            for (int nt = 0; nt < 8; nt++) {
                const int col = wc * 64 + nt * 8 + (lane & 3) * 2;
                float2 p = *(const float2*)&g_Pb[xm * 128 + col];
                float o0 = tanhf(acc[mt][nt][h * 2]     + p.x * mf);
                float o1 = tanhf(acc[mt][nt][h * 2 + 1] + p.y * mf);
                *(float2*)&g_h[(size_t)node * 128 + col] = make_float2(o0, o1);
                acc[mt][nt][h * 2]     = o0;
                acc[mt][nt][h * 2 + 1] = o1;
            }
        }
    __syncthreads();   // all warps done reading As in pass 1
#pragma unroll
    for (int mt = 0; mt < 2; mt++)
#pragma unroll
        for (int h = 0; h < 2; h++) {
            const int r = wr * 32 + mt * 16 + (lane >> 2) + h * 8;
#pragma unroll
            for (int nt = 0; nt < 8; nt++) {
                const int col = wc * 64 + nt * 8 + (lane & 3) * 2;
                As[r * 132 + col]     = acc[mt][nt][h * 2];
                As[r * 132 + col + 1] = acc[mt][nt][h * 2 + 1];
            }
        }
    __syncthreads();

    ACC_ZERO(acc);
    gemm_core(As, g_Bfrag[2], wr, wc, lane, acc);

#pragma unroll
    for (int mt = 0; mt < 2; mt++)
#pragma unroll
        for (int h = 0; h < 2; h++) {
            const int node = s + row0 + wr * 32 + mt * 16 + (lane >> 2) + h * 8;
#pragma unroll
            for (int nt = 0; nt < 8; nt++) {
                const int col = wc * 64 + nt * 8 + (lane & 3) * 2;
                float2 b = *(const float2*)&b_out[col];
                *(float2*)&out[(size_t)node * 128 + col] =
                    make_float2(acc[mt][nt][h * 2] + b.x,
                                acc[mt][nt][h * 2 + 1] + b.y);
            }
        }
}

// ---------------------------------------------------------------------------
// node-level FFMA body: 16 nodes per block-slot, 256 threads
// ---------------------------------------------------------------------------
__device__ __forceinline__ void nodes_body(int base, int s, int e,
                                           const int* __restrict__ x,
                                           const int* __restrict__ mask,
                                           const int* __restrict__ children,
                                           const float* __restrict__ U,
                                           float (*agg)[128])
{
    const int tid = threadIdx.x;
    const int col = tid & 127, half = tid >> 7;

#pragma unroll
    for (int g = 0; g < 8; g++) {
        const int node = base + half * 8 + g;
        const int nb = (node < e) ? node : s;
        float sum = 0.f;
#pragma unroll
        for (int c = 0; c < 8; c++)
            sum += g_h[(size_t)children[(size_t)nb * 8 + c] * 128 + col];
        agg[half * 8 + g][col] = sum;
    }
    __syncthreads();

    float acc[8];
#pragma unroll
    for (int g = 0; g < 8; g++) acc[g] = 0.f;
#pragma unroll 4
    for (int k = 0; k < 128; k++) {
        const float u = __ldg(&U[k * 128 + col]);
#pragma unroll
        for (int g = 0; g < 8; g++)
            acc[g] = fmaf(agg[half * 8 + g][k], u, acc[g]);
    }

#pragma unroll
    for (int g = 0; g < 8; g++) {
        const int node = base + half * 8 + g;
        if (node < e) {
            const float mf = (float)mask[node];
            const int xm = x[node] * mask[node];
            const float hin = g_Pb[(size_t)xm * 128 + col] * mf;
            g_h[(size_t)node * 128 + col] = tanhf(hin + acc[g]);
        }
    }
}

__global__ void __launch_bounds__(256, 4)
k_nodes(int s, int n, const int* __restrict__ x, const int* __restrict__ mask,
        const int* __restrict__ children, const float* __restrict__ U)
{
    __shared__ float agg[16][128];
    nodes_body(s + blockIdx.x * 16, s, s + n, x, mask, children, U, agg);
}

// k_tail: levels 2,1,0 (64+8+1 nodes) in ONE block
__global__ void __launch_bounds__(256, 1)
k_tail(const int* __restrict__ x, const int* __restrict__ mask,
       const int* __restrict__ children, const float* __restrict__ U)
{
    __shared__ float agg[16][128];
    const int ls[3] = {9, 1, 0};
    const int ln[3] = {64, 8, 1};
    for (int lv = 0; lv < 3; lv++) {
        const int s = ls[lv], e = s + ln[lv];
        for (int base = s; base < e; base += 16) {
            nodes_body(base, s, e, x, mask, children, U, agg);
            __syncthreads();
        }
    }
}

// ---------------------------------------------------------------------------
// k_out_t: out[r0 .. r0+nrows) = g_h @ W_out + b_out  (tensor path)
// ---------------------------------------------------------------------------
__global__ void __launch_bounds__(256, 2)
k_out_t(int r0, int nrows, const float* __restrict__ b_out, float* __restrict__ out)
{
    extern __shared__ char sm[];
    float* As = (float*)sm;

    const int tid = threadIdx.x, wid = tid >> 5, lane = tid & 31;
    const int wr = wid & 3, wc = wid >> 2;
    const int row0 = r0 + blockIdx.x * 128;
    const int e = r0 + nrows;

    for (int i = tid; i < 4096; i += 256) {
        int row = i >> 5, q = i & 31;
        int rr = row0 + row; if (rr >= e) rr = e - 1;
        float4 v = ((const float4*)g_h)[(size_t)rr * 32 + q];
        *(float4*)&As[row * 132 + q * 4] = v;
    }
    __syncthreads();

    float acc[2][8][4];
    ACC_ZERO(acc);
    gemm_core(As, g_Bfrag[2], wr, wc, lane, acc);

#pragma unroll
    for (int mt = 0; mt < 2; mt++)
#pragma unroll
        for (int h = 0; h < 2; h++) {
            const int node = row0 + wr * 32 + mt * 16 + (lane >> 2) + h * 8;
            if (node < e) {
#pragma unroll
                for (int nt = 0; nt < 8; nt++) {
                    const int col = wc * 64 + nt * 8 + (lane & 3) * 2;
                    float2 b = *(const float2*)&b_out[col];
                    *(float2*)&out[(size_t)node * 128 + col] =
                        make_float2(acc[mt][nt][h * 2] + b.x,
                                    acc[mt][nt][h * 2 + 1] + b.y);
                }
            }
        }
}

// ---------------------------------------------------------------------------
// k_out_leaf: out[leaf] = mask * Q[x] + b_out  (8192 blocks x 4 float4/thread)
// ---------------------------------------------------------------------------
__global__ void __launch_bounds__(256)
k_out_leaf(const int* __restrict__ x, const int* __restrict__ mask,
           const float* __restrict__ b_out, float* __restrict__ out)
{
    const float4 bv = ((const float4*)b_out)[threadIdx.x & 31];
    int idx = blockIdx.x * 256 + threadIdx.x;
#pragma unroll
    for (int it = 0; it < 4; it++, idx += 8192 * 256) {
        const int rr = idx >> 5, c = idx & 31;
        const int node = NINT + rr;
        const int m = mask[node];
        const int xm = x[node] * m;
        const float mf = (float)m;
        float4 q = ((const float4*)g_Q)[(size_t)xm * 32 + c];
        float4 o = make_float4(fmaf(q.x, mf, bv.x), fmaf(q.y, mf, bv.y),
                               fmaf(q.z, mf, bv.z), fmaf(q.w, mf, bv.w));
        ((float4*)out)[(size_t)node * 32 + c] = o;
    }
}

// ---------------------------------------------------------------------------
extern "C" void kernel_launch(void* const* d_in, const int* in_sizes, int n_in,
                              void* d_out, int out_size)
{
    const int*   x        = (const int*)  d_in[0];
    const int*   mask     = (const int*)  d_in[1];
    const int*   children = (const int*)  d_in[2];
    const float* emb      = (const float*)d_in[3];
    const float* W_in     = (const float*)d_in[4];
    const float* b_in     = (const float*)d_in[5];
    const float* U        = (const float*)d_in[6];
    const float* W_out    = (const float*)d_in[7];
    const float* b_out    = (const float*)d_in[8];
    float*       out      = (float*)d_out;
    (void)in_sizes; (void)n_in; (void)out_size;

    static cudaStream_t sA = nullptr;
    static cudaEvent_t  eV, eJ;
    if (!sA) {
        cudaStreamCreateWithFlags(&sA, cudaStreamNonBlocking);
        cudaEventCreateWithFlags(&eV, cudaEventDisableTiming);
        cudaEventCreateWithFlags(&eJ, cudaEventDisableTiming);
        cudaFuncSetAttribute(k_vocab,   cudaFuncAttributeMaxDynamicSharedMemorySize, SMEM_BYTES);
        cudaFuncSetAttribute(k_level5f, cudaFuncAttributeMaxDynamicSharedMemorySize, SMEM_BYTES);
        cudaFuncSetAttribute(k_out_t,   cudaFuncAttributeMaxDynamicSharedMemorySize, SMEM_BYTES);
    }
    cudaStream_t s0 = 0;

    k_prep<<<96, 256, 0, s0>>>(W_in, U, W_out);
    k_vocab<<<250, 256, SMEM_BYTES, s0>>>(emb, b_in);

    // fork: leaf outputs depend only on g_Q
    cudaEventRecord(eV, s0);
    cudaStreamWaitEvent(sA, eV, 0);
    k_out_leaf<<<8192, 256, 0, sA>>>(x, mask, b_out, out);

    // main chain
    k_level5f<<<256, 256, SMEM_BYTES, s0>>>(4681, x, mask, children, b_out, out);
    k_nodes<<<256, 256, 0, s0>>>(585, 4096, x, mask, children, U); // L4
    k_nodes<<< 32, 256, 0, s0>>>( 73,  512, x, mask, children, U); // L3
    k_tail <<<  1, 256, 0, s0>>>(x, mask, children, U);            // L2..L0
    k_out_t<<<37, 256, SMEM_BYTES, s0>>>(0, 4681, b_out, out);     // out rows 0..4681

    // join
    cudaEventRecord(eJ, sA);
    cudaStreamWaitEvent(s0, eJ, 0);
}

// round 8
// speedup vs baseline: 1.3351x; 1.2271x over previous
#include <cuda_runtime.h>
#include <cuda_bf16.h>
#include <math.h>
#include <stdint.h>

#define NINT 37449
#define NVOC 32000

// ---------------- device scratch (no allocs allowed) ----------------
static __device__ float g_Pb[(size_t)NVOC * 128]; // emb@W_in + b_in
static __device__ float g_T [(size_t)NVOC * 128]; // tanh(Pb)
static __device__ float g_Q [(size_t)NVOC * 128]; // T@W_out
static __device__ float g_h [(size_t)NINT * 128]; // hidden, internal nodes
static __device__ uint4 g_Bfrag[3][4096];         // {Win,U,Wout}: {bh0,bh1,bl0,bl1} packed bf16x2

// smem: AsH[128][68] + AsL[128][68] packed bf16x2 (hi / lo split of A)
#define KP 68
#define SMEM_BYTES (128 * KP * 4 * 2)   // 69632

// pack two floats -> bf16x2 (v0 in low half)
__device__ __forceinline__ uint32_t pack_bf(float v0, float v1) {
    uint32_t r;
    asm("cvt.rn.bf16x2.f32 %0, %1, %2;" : "=r"(r) : "f"(v1), "f"(v0));
    return r;
}
__device__ __forceinline__ float bfv(float v) {           // float(bf16(v))
    return __bfloat162float(__float2bfloat16(v));
}

// store 4 consecutive k-values (float4) as hi/lo packed bf16x2 pairs
__device__ __forceinline__ void store_k4(uint32_t* AsH, uint32_t* AsL,
                                         int row, int f4, float4 v) {
    float h0 = bfv(v.x), h1 = bfv(v.y), h2 = bfv(v.z), h3 = bfv(v.w);
    const int o = row * KP + f4 * 2;
    AsH[o]     = pack_bf(h0, h1);
    AsH[o + 1] = pack_bf(h2, h3);
    AsL[o]     = pack_bf(v.x - h0, v.y - h1);
    AsL[o + 1] = pack_bf(v.z - h2, v.w - h3);
}

__device__ __forceinline__ void mma16(float d[4], const uint32_t a[4],
                                      uint32_t b0, uint32_t b1) {
    asm volatile(
        "mma.sync.aligned.m16n8k16.row.col.f32.bf16.bf16.f32 "
        "{%0,%1,%2,%3}, {%4,%5,%6,%7}, {%8,%9}, {%0,%1,%2,%3};"
        : "+f"(d[0]), "+f"(d[1]), "+f"(d[2]), "+f"(d[3])
        : "r"(a[0]), "r"(a[1]), "r"(a[2]), "r"(a[3]), "r"(b0), "r"(b1));
}

// 128x128x128 tile GEMM, bf16 x3 (AhBh + AhBl + AlBh), A pre-split in smem.
// Warp (wr,wc): rows wr*32..+32, cols wc*64..+64.
__device__ __forceinline__ void gemm_core(const uint32_t* __restrict__ AsH,
                                          const uint32_t* __restrict__ AsL,
                                          const uint4* __restrict__ Bf,
                                          int wr, int wc, int lane,
                                          float acc[2][8][4])
{
    const int rA = wr * 32 + (lane >> 2);
    const int cA = lane & 3;
#pragma unroll
    for (int ks = 0; ks < 8; ks++) {
        uint32_t ah[2][4], al[2][4];
        const int kpb = ks * 8 + cA;
#pragma unroll
        for (int mt = 0; mt < 2; mt++) {
            const int r = rA + mt * 16;
            ah[mt][0] = AsH[r * KP + kpb];
            ah[mt][1] = AsH[(r + 8) * KP + kpb];
            ah[mt][2] = AsH[r * KP + kpb + 4];
            ah[mt][3] = AsH[(r + 8) * KP + kpb + 4];
            al[mt][0] = AsL[r * KP + kpb];
            al[mt][1] = AsL[(r + 8) * KP + kpb];
            al[mt][2] = AsL[r * KP + kpb + 4];
            al[mt][3] = AsL[(r + 8) * KP + kpb + 4];
        }
#pragma unroll
        for (int nt = 0; nt < 8; nt++) {
            uint4 b = __ldg(&Bf[(ks * 16 + wc * 8 + nt) * 32 + lane]);
#pragma unroll
            for (int mt = 0; mt < 2; mt++) {
                mma16(acc[mt][nt], ah[mt], b.x, b.y);
                mma16(acc[mt][nt], ah[mt], b.z, b.w);
                mma16(acc[mt][nt], al[mt], b.x, b.y);
            }
        }
    }
}

#define ACC_ZERO(acc) do { \
    _Pragma("unroll") for (int _a = 0; _a < 2; _a++) \
    _Pragma("unroll") for (int _b = 0; _b < 8; _b++) \
    _Pragma("unroll") for (int _c = 0; _c < 4; _c++) acc[_a][_b][_c] = 0.f; } while (0)

// ---------------------------------------------------------------------------
// k_prep: bf16-split packed B fragments (B[n][k] = W[k][n], col-major frags).
// index [w][(ks*16+ng)*32 + lane]: n = ng*8+lane/4, k0 = ks*16+(lane%4)*2
// ---------------------------------------------------------------------------
__global__ void k_prep(const float* __restrict__ Win, const float* __restrict__ U,
                       const float* __restrict__ Wout)
{
    int i = blockIdx.x * 256 + threadIdx.x;
    if (i < 3 * 4096) {
        int w = i >> 12, r = i & 4095;
        int ks = r >> 9, ng = (r >> 5) & 15, lane = r & 31;
        int n = ng * 8 + (lane >> 2);
        int k0 = ks * 16 + (lane & 3) * 2;
        const float* W = (w == 0) ? Win : ((w == 1) ? U : Wout);
        float v00 = W[k0 * 128 + n],       v01 = W[(k0 + 1) * 128 + n];
        float v10 = W[(k0 + 8) * 128 + n], v11 = W[(k0 + 9) * 128 + n];
        float h00 = bfv(v00), h01 = bfv(v01), h10 = bfv(v10), h11 = bfv(v11);
        g_Bfrag[w][r] = make_uint4(pack_bf(h00, h01), pack_bf(h10, h11),
                                   pack_bf(v00 - h00, v01 - h01),
                                   pack_bf(v10 - h10, v11 - h11));
    }
}

// ---------------------------------------------------------------------------
// k_vocab: Pb = emb@W_in + b_in; T = tanh(Pb); Q = T@W_out  (128 rows/block)
// ---------------------------------------------------------------------------
__global__ void __launch_bounds__(256, 2)
k_vocab(const float* __restrict__ emb, const float* __restrict__ b_in)
{
    extern __shared__ uint32_t sm[];
    uint32_t* AsH = sm;
    uint32_t* AsL = sm + 128 * KP;

    const int tid = threadIdx.x, wid = tid >> 5, lane = tid & 31;
    const int wr = wid & 3, wc = wid >> 2;
    const int row0 = blockIdx.x * 128;

    for (int i = tid; i < 4096; i += 256) {
        int row = i >> 5, q = i & 31;
        float4 v = ((const float4*)emb)[(size_t)(row0 + row) * 32 + q];
        store_k4(AsH, AsL, row, q, v);
    }
    __syncthreads();

    float acc[2][8][4];
    ACC_ZERO(acc);
    gemm_core(AsH, AsL, g_Bfrag[0], wr, wc, lane, acc);

    // epilogue 1: Pb, T; keep tanh in acc
#pragma unroll
    for (int mt = 0; mt < 2; mt++)
#pragma unroll
        for (int h = 0; h < 2; h++) {
            const size_t node = row0 + wr * 32 + mt * 16 + (lane >> 2) + h * 8;
#pragma unroll
            for (int nt = 0; nt < 8; nt++) {
                const int col = wc * 64 + nt * 8 + (lane & 3) * 2;
                float2 b = *(const float2*)&b_in[col];
                float p0 = acc[mt][nt][h * 2]     + b.x;
                float p1 = acc[mt][nt][h * 2 + 1] + b.y;
                *(float2*)&g_Pb[node * 128 + col] = make_float2(p0, p1);
                float t0 = tanhf(p0), t1 = tanhf(p1);
                *(float2*)&g_T[node * 128 + col] = make_float2(t0, t1);
                acc[mt][nt][h * 2]     = t0;
                acc[mt][nt][h * 2 + 1] = t1;
            }
        }
    __syncthreads();   // all warps done READING As in pass 1
#pragma unroll
    for (int mt = 0; mt < 2; mt++)
#pragma unroll
        for (int h = 0; h < 2; h++) {
            const int r = wr * 32 + mt * 16 + (lane >> 2) + h * 8;
#pragma unroll
            for (int nt = 0; nt < 8; nt++) {
                const int col = wc * 64 + nt * 8 + (lane & 3) * 2;
                float t0 = acc[mt][nt][h * 2], t1 = acc[mt][nt][h * 2 + 1];
                float h0 = bfv(t0), h1 = bfv(t1);
                AsH[r * KP + (col >> 1)] = pack_bf(h0, h1);
                AsL[r * KP + (col >> 1)] = pack_bf(t0 - h0, t1 - h1);
            }
        }
    __syncthreads();

    ACC_ZERO(acc);
    gemm_core(AsH, AsL, g_Bfrag[2], wr, wc, lane, acc);

#pragma unroll
    for (int mt = 0; mt < 2; mt++)
#pragma unroll
        for (int h = 0; h < 2; h++) {
            const size_t node = row0 + wr * 32 + mt * 16 + (lane >> 2) + h * 8;
#pragma unroll
            for (int nt = 0; nt < 8; nt++) {
                const int col = wc * 64 + nt * 8 + (lane & 3) * 2;
                *(float2*)&g_Q[node * 128 + col] =
                    make_float2(acc[mt][nt][h * 2], acc[mt][nt][h * 2 + 1]);
            }
        }
}

// ---------------------------------------------------------------------------
// k_level5f: h = tanh(Pb[x*m]*m + (sum_c m_c*T[x_c]) @ U), then fused
//            out[node] = h @ W_out + b_out  (rows 4681..37449)
// ---------------------------------------------------------------------------
__global__ void __launch_bounds__(256, 2)
k_level5f(int s, const int* __restrict__ x, const int* __restrict__ mask,
          const int* __restrict__ children, const float* __restrict__ b_out,
          float* __restrict__ out)
{
    extern __shared__ uint32_t sm[];
    uint32_t* AsH = sm;
    uint32_t* AsL = sm + 128 * KP;

    const int tid = threadIdx.x, wid = tid >> 5, lane = tid & 31;
    const int wr = wid & 3, wc = wid >> 2;
    const int row0 = blockIdx.x * 128;

    for (int i = tid; i < 4096; i += 256) {
        int row = i >> 5, f4 = i & 31;
        int node = s + row0 + row;
        float4 acc4 = make_float4(0.f, 0.f, 0.f, 0.f);
#pragma unroll
        for (int c = 0; c < 8; c++) {
            int cc = children[(size_t)node * 8 + c];
            int mm = mask[cc];
            float fm = (float)mm;
            float4 t = ((const float4*)g_T)[(size_t)(x[cc] * mm) * 32 + f4];
            acc4.x = fmaf(t.x, fm, acc4.x); acc4.y = fmaf(t.y, fm, acc4.y);
            acc4.z = fmaf(t.z, fm, acc4.z); acc4.w = fmaf(t.w, fm, acc4.w);
        }
        store_k4(AsH, AsL, row, f4, acc4);
    }
    __syncthreads();

    float acc[2][8][4];
    ACC_ZERO(acc);
    gemm_core(AsH, AsL, g_Bfrag[1], wr, wc, lane, acc);

    // epilogue 1: h = tanh(acc + Pb*m); write g_h; keep h in acc
#pragma unroll
    for (int mt = 0; mt < 2; mt++)
#pragma unroll
        for (int h = 0; h < 2; h++) {
            const int node = s + row0 + wr * 32 + mt * 16 + (lane >> 2) + h * 8;
            const float mf = (float)mask[node];
            const size_t xm = (size_t)(x[node] * mask[node]);
#pragma unroll
            for (int nt = 0; nt < 8; nt++) {
                const int col = wc * 64 + nt * 8 + (lane & 3) * 2;
                float2 p = *(const float2*)&g_Pb[xm * 128 + col];
                float o0 = tanhf(acc[mt][nt][h * 2]     + p.x * mf);
                float o1 = tanhf(acc[mt][nt][h * 2 + 1] + p.y * mf);
                *(float2*)&g_h[(size_t)node * 128 + col] = make_float2(o0, o1);
                acc[mt][nt][h * 2]     = o0;
                acc[mt][nt][h * 2 + 1] = o1;
            }
        }
    __syncthreads();
#pragma unroll
    for (int mt = 0; mt < 2; mt++)
#pragma unroll
        for (int h = 0; h < 2; h++) {
            const int r = wr * 32 + mt * 16 + (lane >> 2) + h * 8;
#pragma unroll
            for (int nt = 0; nt < 8; nt++) {
                const int col = wc * 64 + nt * 8 + (lane & 3) * 2;
                float t0 = acc[mt][nt][h * 2], t1 = acc[mt][nt][h * 2 + 1];
                float h0 = bfv(t0), h1 = bfv(t1);
                AsH[r * KP + (col >> 1)] = pack_bf(h0, h1);
                AsL[r * KP + (col >> 1)] = pack_bf(t0 - h0, t1 - h1);
            }
        }
    __syncthreads();

    ACC_ZERO(acc);
    gemm_core(AsH, AsL, g_Bfrag[2], wr, wc, lane, acc);

#pragma unroll
    for (int mt = 0; mt < 2; mt++)
#pragma unroll
        for (int h = 0; h < 2; h++) {
            const int node = s + row0 + wr * 32 + mt * 16 + (lane >> 2) + h * 8;
#pragma unroll
            for (int nt = 0; nt < 8; nt++) {
                const int col = wc * 64 + nt * 8 + (lane & 3) * 2;
                float2 b = *(const float2*)&b_out[col];
                *(float2*)&out[(size_t)node * 128 + col] =
                    make_float2(acc[mt][nt][h * 2] + b.x,
                                acc[mt][nt][h * 2 + 1] + b.y);
            }
        }
}

// ---------------------------------------------------------------------------
// node-level FFMA body: 16 nodes per block-slot, 256 threads
// ---------------------------------------------------------------------------
__device__ __forceinline__ void nodes_body(int base, int s, int e,
                                           const int* __restrict__ x,
                                           const int* __restrict__ mask,
                                           const int* __restrict__ children,
                                           const float* __restrict__ U,
                                           float (*agg)[128])
{
    const int tid = threadIdx.x;
    const int col = tid & 127, half = tid >> 7;

#pragma unroll
    for (int g = 0; g < 8; g++) {
        const int node = base + half * 8 + g;
        const int nb = (node < e) ? node : s;
        float sum = 0.f;
#pragma unroll
        for (int c = 0; c < 8; c++)
            sum += g_h[(size_t)children[(size_t)nb * 8 + c] * 128 + col];
        agg[half * 8 + g][col] = sum;
    }
    __syncthreads();

    float acc[8];
#pragma unroll
    for (int g = 0; g < 8; g++) acc[g] = 0.f;
#pragma unroll 4
    for (int k = 0; k < 128; k++) {
        const float u = __ldg(&U[k * 128 + col]);
#pragma unroll
        for (int g = 0; g < 8; g++)
            acc[g] = fmaf(agg[half * 8 + g][k], u, acc[g]);
    }

#pragma unroll
    for (int g = 0; g < 8; g++) {
        const int node = base + half * 8 + g;
        if (node < e) {
            const float mf = (float)mask[node];
            const int xm = x[node] * mask[node];
            const float hin = g_Pb[(size_t)xm * 128 + col] * mf;
            g_h[(size_t)node * 128 + col] = tanhf(hin + acc[g]);
        }
    }
}

__global__ void __launch_bounds__(256, 4)
k_nodes(int s, int n, const int* __restrict__ x, const int* __restrict__ mask,
        const int* __restrict__ children, const float* __restrict__ U)
{
    __shared__ float agg[16][128];
    nodes_body(s + blockIdx.x * 16, s, s + n, x, mask, children, U, agg);
}

// k_tail: levels 2,1,0 (64+8+1 nodes) in ONE block
__global__ void __launch_bounds__(256, 1)
k_tail(const int* __restrict__ x, const int* __restrict__ mask,
       const int* __restrict__ children, const float* __restrict__ U)
{
    __shared__ float agg[16][128];
    const int ls[3] = {9, 1, 0};
    const int ln[3] = {64, 8, 1};
    for (int lv = 0; lv < 3; lv++) {
        const int s = ls[lv], e = s + ln[lv];
        for (int base = s; base < e; base += 16) {
            nodes_body(base, s, e, x, mask, children, U, agg);
            __syncthreads();
        }
    }
}

// ---------------------------------------------------------------------------
// k_out_t: out[r0 .. r0+nrows) = g_h @ W_out + b_out  (tensor path)
// ---------------------------------------------------------------------------
__global__ void __launch_bounds__(256, 2)
k_out_t(int r0, int nrows, const float* __restrict__ b_out, float* __restrict__ out)
{
    extern __shared__ uint32_t sm[];
    uint32_t* AsH = sm;
    uint32_t* AsL = sm + 128 * KP;

    const int tid = threadIdx.x, wid = tid >> 5, lane = tid & 31;
    const int wr = wid & 3, wc = wid >> 2;
    const int row0 = r0 + blockIdx.x * 128;
    const int e = r0 + nrows;

    for (int i = tid; i < 4096; i += 256) {
        int row = i >> 5, q = i & 31;
        int rr = row0 + row; if (rr >= e) rr = e - 1;
        float4 v = ((const float4*)g_h)[(size_t)rr * 32 + q];
        store_k4(AsH, AsL, row, q, v);
    }
    __syncthreads();

    float acc[2][8][4];
    ACC_ZERO(acc);
    gemm_core(AsH, AsL, g_Bfrag[2], wr, wc, lane, acc);

#pragma unroll
    for (int mt = 0; mt < 2; mt++)
#pragma unroll
        for (int h = 0; h < 2; h++) {
            const int node = row0 + wr * 32 + mt * 16 + (lane >> 2) + h * 8;
            if (node < e) {
#pragma unroll
                for (int nt = 0; nt < 8; nt++) {
                    const int col = wc * 64 + nt * 8 + (lane & 3) * 2;
                    float2 b = *(const float2*)&b_out[col];
                    *(float2*)&out[(size_t)node * 128 + col] =
                        make_float2(acc[mt][nt][h * 2] + b.x,
                                    acc[mt][nt][h * 2 + 1] + b.y);
                }
            }
        }
}

// ---------------------------------------------------------------------------
// k_out_leaf: out[leaf] = mask * Q[x] + b_out
// ---------------------------------------------------------------------------
__global__ void __launch_bounds__(256)
k_out_leaf(const int* __restrict__ x, const int* __restrict__ mask,
           const float* __restrict__ b_out, float* __restrict__ out)
{
    const float4 bv = ((const float4*)b_out)[threadIdx.x & 31];
    int idx = blockIdx.x * 256 + threadIdx.x;
#pragma unroll
    for (int it = 0; it < 4; it++, idx += 8192 * 256) {
        const int rr = idx >> 5, c = idx & 31;
        const int node = NINT + rr;
        const int m = mask[node];
        const int xm = x[node] * m;
        const float mf = (float)m;
        float4 q = ((const float4*)g_Q)[(size_t)xm * 32 + c];
        float4 o = make_float4(fmaf(q.x, mf, bv.x), fmaf(q.y, mf, bv.y),
                               fmaf(q.z, mf, bv.z), fmaf(q.w, mf, bv.w));
        ((float4*)out)[(size_t)node * 32 + c] = o;
    }
}

// ---------------------------------------------------------------------------
extern "C" void kernel_launch(void* const* d_in, const int* in_sizes, int n_in,
                              void* d_out, int out_size)
{
    const int*   x        = (const int*)  d_in[0];
    const int*   mask     = (const int*)  d_in[1];
    const int*   children = (const int*)  d_in[2];
    const float* emb      = (const float*)d_in[3];
    const float* W_in     = (const float*)d_in[4];
    const float* b_in     = (const float*)d_in[5];
    const float* U        = (const float*)d_in[6];
    const float* W_out    = (const float*)d_in[7];
    const float* b_out    = (const float*)d_in[8];
    float*       out      = (float*)d_out;
    (void)in_sizes; (void)n_in; (void)out_size;

    static cudaStream_t sA = nullptr;
    static cudaEvent_t  eV, eJ;
    if (!sA) {
        cudaStreamCreateWithFlags(&sA, cudaStreamNonBlocking);
        cudaEventCreateWithFlags(&eV, cudaEventDisableTiming);
        cudaEventCreateWithFlags(&eJ, cudaEventDisableTiming);
        cudaFuncSetAttribute(k_vocab,   cudaFuncAttributeMaxDynamicSharedMemorySize, SMEM_BYTES);
        cudaFuncSetAttribute(k_level5f, cudaFuncAttributeMaxDynamicSharedMemorySize, SMEM_BYTES);
        cudaFuncSetAttribute(k_out_t,   cudaFuncAttributeMaxDynamicSharedMemorySize, SMEM_BYTES);
    }
    cudaStream_t s0 = 0;

    k_prep<<<48, 256, 0, s0>>>(W_in, U, W_out);
    k_vocab<<<250, 256, SMEM_BYTES, s0>>>(emb, b_in);

    // fork: leaf outputs depend only on g_Q
    cudaEventRecord(eV, s0);
    cudaStreamWaitEvent(sA, eV, 0);
    k_out_leaf<<<8192, 256, 0, sA>>>(x, mask, b_out, out);

    // main chain
    k_level5f<<<256, 256, SMEM_BYTES, s0>>>(4681, x, mask, children, b_out, out);
    k_nodes<<<256, 256, 0, s0>>>(585, 4096, x, mask, children, U); // L4
    k_nodes<<< 32, 256, 0, s0>>>( 73,  512, x, mask, children, U); // L3
    k_tail <<<  1, 256, 0, s0>>>(x, mask, children, U);            // L2..L0
    k_out_t<<<37, 256, SMEM_BYTES, s0>>>(0, 4681, b_out, out);     // out rows 0..4681

    // join
    cudaEventRecord(eJ, sA);
    cudaStreamWaitEvent(s0, eJ, 0);
}

// round 9
// speedup vs baseline: 1.3415x; 1.0048x over previous
#include <cuda_runtime.h>
#include <cuda_bf16.h>
#include <math.h>
#include <stdint.h>

#define NINT 37449
#define NVOC 32000

// ---------------- device scratch (no allocs allowed) ----------------
static __device__ float g_Pb[(size_t)NVOC * 128]; // emb@W_in + b_in
static __device__ float g_T [(size_t)NVOC * 128]; // tanh(Pb)
static __device__ float g_Q [(size_t)NVOC * 128]; // T@W_out
static __device__ float g_h [(size_t)NINT * 128]; // hidden, internal nodes
static __device__ uint4 g_Bfrag[3][4096];         // {Win,U,Wout}: {bh0,bh1,bl0,bl1} packed bf16x2

// smem: AsH[64][68] + AsL[64][68] packed bf16x2 (hi/lo split of A)
#define KP 68
#define SMEM_BYTES (64 * KP * 4 * 2)   // 34816

__device__ __forceinline__ uint32_t pack_bf(float v0, float v1) {
    uint32_t r;
    asm("cvt.rn.bf16x2.f32 %0, %1, %2;" : "=r"(r) : "f"(v1), "f"(v0));
    return r;
}
__device__ __forceinline__ float bfv(float v) {
    return __bfloat162float(__float2bfloat16(v));
}

__device__ __forceinline__ void store_k4(uint32_t* AsH, uint32_t* AsL,
                                         int row, int f4, float4 v) {
    float h0 = bfv(v.x), h1 = bfv(v.y), h2 = bfv(v.z), h3 = bfv(v.w);
    const int o = row * KP + f4 * 2;
    AsH[o]     = pack_bf(h0, h1);
    AsH[o + 1] = pack_bf(h2, h3);
    AsL[o]     = pack_bf(v.x - h0, v.y - h1);
    AsL[o + 1] = pack_bf(v.z - h2, v.w - h3);
}

__device__ __forceinline__ void mma16(float d[4], const uint32_t a[4],
                                      uint32_t b0, uint32_t b1) {
    asm volatile(
        "mma.sync.aligned.m16n8k16.row.col.f32.bf16.bf16.f32 "
        "{%0,%1,%2,%3}, {%4,%5,%6,%7}, {%8,%9}, {%0,%1,%2,%3};"
        : "+f"(d[0]), "+f"(d[1]), "+f"(d[2]), "+f"(d[3])
        : "r"(a[0]), "r"(a[1]), "r"(a[2]), "r"(a[3]), "r"(b0), "r"(b1));
}

// 64x128x128 tile GEMM, bf16 x3 (AhBh + AhBl + AlBh), A pre-split in smem.
// Warp (wr,wc): rows wr*16..+16, cols wc*64..+64.
__device__ __forceinline__ void gemm64(const uint32_t* __restrict__ AsH,
                                       const uint32_t* __restrict__ AsL,
                                       const uint4* __restrict__ Bf,
                                       int wr, int wc, int lane,
                                       float acc[8][4])
{
    const int rA = wr * 16 + (lane >> 2);
    const int cA = lane & 3;
#pragma unroll
    for (int ks = 0; ks < 8; ks++) {
        uint32_t ah[4], al[4];
        const int kpb = ks * 8 + cA;
        ah[0] = AsH[rA * KP + kpb];
        ah[1] = AsH[(rA + 8) * KP + kpb];
        ah[2] = AsH[rA * KP + kpb + 4];
        ah[3] = AsH[(rA + 8) * KP + kpb + 4];
        al[0] = AsL[rA * KP + kpb];
        al[1] = AsL[(rA + 8) * KP + kpb];
        al[2] = AsL[rA * KP + kpb + 4];
        al[3] = AsL[(rA + 8) * KP + kpb + 4];
#pragma unroll
        for (int nt = 0; nt < 8; nt++) {
            uint4 b = __ldg(&Bf[(ks * 16 + wc * 8 + nt) * 32 + lane]);
            mma16(acc[nt], ah, b.x, b.y);
            mma16(acc[nt], ah, b.z, b.w);
            mma16(acc[nt], al, b.x, b.y);
        }
    }
}

#define ACC_ZERO8(acc) do { \
    _Pragma("unroll") for (int _b = 0; _b < 8; _b++) \
    _Pragma("unroll") for (int _c = 0; _c < 4; _c++) acc[_b][_c] = 0.f; } while (0)

// ---------------------------------------------------------------------------
// k_prep: bf16-split packed B fragments (B[n][k] = W[k][n]).
// ---------------------------------------------------------------------------
__global__ void k_prep(const float* __restrict__ Win, const float* __restrict__ U,
                       const float* __restrict__ Wout)
{
    int i = blockIdx.x * 256 + threadIdx.x;
    if (i < 3 * 4096) {
        int w = i >> 12, r = i & 4095;
        int ks = r >> 9, ng = (r >> 5) & 15, lane = r & 31;
        int n = ng * 8 + (lane >> 2);
        int k0 = ks * 16 + (lane & 3) * 2;
        const float* W = (w == 0) ? Win : ((w == 1) ? U : Wout);
        float v00 = W[k0 * 128 + n],       v01 = W[(k0 + 1) * 128 + n];
        float v10 = W[(k0 + 8) * 128 + n], v11 = W[(k0 + 9) * 128 + n];
        float h00 = bfv(v00), h01 = bfv(v01), h10 = bfv(v10), h11 = bfv(v11);
        g_Bfrag[w][r] = make_uint4(pack_bf(h00, h01), pack_bf(h10, h11),
                                   pack_bf(v00 - h00, v01 - h01),
                                   pack_bf(v10 - h10, v11 - h11));
    }
}

// ---------------------------------------------------------------------------
// k_vocab1: Pb = emb@W_in + b_in; T = tanh(Pb)   (64 rows/block)
// ---------------------------------------------------------------------------
__global__ void __launch_bounds__(256, 3)
k_vocab1(const float* __restrict__ emb, const float* __restrict__ b_in)
{
    extern __shared__ uint32_t sm[];
    uint32_t* AsH = sm;
    uint32_t* AsL = sm + 64 * KP;

    const int tid = threadIdx.x, wid = tid >> 5, lane = tid & 31;
    const int wr = wid & 3, wc = wid >> 2;
    const int row0 = blockIdx.x * 64;

    for (int i = tid; i < 2048; i += 256) {
        int row = i >> 5, q = i & 31;
        float4 v = ((const float4*)emb)[(size_t)(row0 + row) * 32 + q];
        store_k4(AsH, AsL, row, q, v);
    }
    __syncthreads();

    float acc[8][4];
    ACC_ZERO8(acc);
    gemm64(AsH, AsL, g_Bfrag[0], wr, wc, lane, acc);

#pragma unroll
    for (int h = 0; h < 2; h++) {
        const size_t node = row0 + wr * 16 + (lane >> 2) + h * 8;
#pragma unroll
        for (int nt = 0; nt < 8; nt++) {
            const int col = wc * 64 + nt * 8 + (lane & 3) * 2;
            float2 b = *(const float2*)&b_in[col];
            float p0 = acc[nt][h * 2]     + b.x;
            float p1 = acc[nt][h * 2 + 1] + b.y;
            *(float2*)&g_Pb[node * 128 + col] = make_float2(p0, p1);
            *(float2*)&g_T[node * 128 + col] = make_float2(tanhf(p0), tanhf(p1));
        }
    }
}

// ---------------------------------------------------------------------------
// k_vocab2: Q = T @ W_out  (64 rows/block, reads g_T)
// ---------------------------------------------------------------------------
__global__ void __launch_bounds__(256, 3)
k_vocab2()
{
    extern __shared__ uint32_t sm[];
    uint32_t* AsH = sm;
    uint32_t* AsL = sm + 64 * KP;

    const int tid = threadIdx.x, wid = tid >> 5, lane = tid & 31;
    const int wr = wid & 3, wc = wid >> 2;
    const int row0 = blockIdx.x * 64;

    for (int i = tid; i < 2048; i += 256) {
        int row = i >> 5, q = i & 31;
        float4 v = ((const float4*)g_T)[(size_t)(row0 + row) * 32 + q];
        store_k4(AsH, AsL, row, q, v);
    }
    __syncthreads();

    float acc[8][4];
    ACC_ZERO8(acc);
    gemm64(AsH, AsL, g_Bfrag[2], wr, wc, lane, acc);

#pragma unroll
    for (int h = 0; h < 2; h++) {
        const size_t node = row0 + wr * 16 + (lane >> 2) + h * 8;
#pragma unroll
        for (int nt = 0; nt < 8; nt++) {
            const int col = wc * 64 + nt * 8 + (lane & 3) * 2;
            *(float2*)&g_Q[node * 128 + col] =
                make_float2(acc[nt][h * 2], acc[nt][h * 2 + 1]);
        }
    }
}

// ---------------------------------------------------------------------------
// k_level5: h[node] = tanh(Pb[x*m]*m + (sum_c m_c*T[x_c]) @ U)  (64 rows/block)
// ---------------------------------------------------------------------------
__global__ void __launch_bounds__(256, 3)
k_level5(int s, const int* __restrict__ x, const int* __restrict__ mask,
         const int* __restrict__ children)
{
    extern __shared__ uint32_t sm[];
    uint32_t* AsH = sm;
    uint32_t* AsL = sm + 64 * KP;

    const int tid = threadIdx.x, wid = tid >> 5, lane = tid & 31;
    const int wr = wid & 3, wc = wid >> 2;
    const int row0 = blockIdx.x * 64;

    for (int i = tid; i < 2048; i += 256) {
        int row = i >> 5, f4 = i & 31;
        int node = s + row0 + row;
        float4 acc4 = make_float4(0.f, 0.f, 0.f, 0.f);
#pragma unroll
        for (int c = 0; c < 8; c++) {
            int cc = children[(size_t)node * 8 + c];
            int mm = mask[cc];
            float fm = (float)mm;
            float4 t = ((const float4*)g_T)[(size_t)(x[cc] * mm) * 32 + f4];
            acc4.x = fmaf(t.x, fm, acc4.x); acc4.y = fmaf(t.y, fm, acc4.y);
            acc4.z = fmaf(t.z, fm, acc4.z); acc4.w = fmaf(t.w, fm, acc4.w);
        }
        store_k4(AsH, AsL, row, f4, acc4);
    }
    __syncthreads();

    float acc[8][4];
    ACC_ZERO8(acc);
    gemm64(AsH, AsL, g_Bfrag[1], wr, wc, lane, acc);

#pragma unroll
    for (int h = 0; h < 2; h++) {
        const int node = s + row0 + wr * 16 + (lane >> 2) + h * 8;
        const float mf = (float)mask[node];
        const size_t xm = (size_t)(x[node] * mask[node]);
#pragma unroll
        for (int nt = 0; nt < 8; nt++) {
            const int col = wc * 64 + nt * 8 + (lane & 3) * 2;
            float2 p = *(const float2*)&g_Pb[xm * 128 + col];
            float o0 = tanhf(acc[nt][h * 2]     + p.x * mf);
            float o1 = tanhf(acc[nt][h * 2 + 1] + p.y * mf);
            *(float2*)&g_h[(size_t)node * 128 + col] = make_float2(o0, o1);
        }
    }
}

// ---------------------------------------------------------------------------
// k_out_t: out[r0 .. r0+nrows) = g_h @ W_out + b_out  (64 rows/block)
// ---------------------------------------------------------------------------
__global__ void __launch_bounds__(256, 3)
k_out_t(int r0, int nrows, const float* __restrict__ b_out, float* __restrict__ out)
{
    extern __shared__ uint32_t sm[];
    uint32_t* AsH = sm;
    uint32_t* AsL = sm + 64 * KP;

    const int tid = threadIdx.x, wid = tid >> 5, lane = tid & 31;
    const int wr = wid & 3, wc = wid >> 2;
    const int row0 = r0 + blockIdx.x * 64;
    const int e = r0 + nrows;

    for (int i = tid; i < 2048; i += 256) {
        int row = i >> 5, q = i & 31;
        int rr = row0 + row; if (rr >= e) rr = e - 1;
        float4 v = ((const float4*)g_h)[(size_t)rr * 32 + q];
        store_k4(AsH, AsL, row, q, v);
    }
    __syncthreads();

    float acc[8][4];
    ACC_ZERO8(acc);
    gemm64(AsH, AsL, g_Bfrag[2], wr, wc, lane, acc);

#pragma unroll
    for (int h = 0; h < 2; h++) {
        const int node = row0 + wr * 16 + (lane >> 2) + h * 8;
        if (node < e) {
#pragma unroll
            for (int nt = 0; nt < 8; nt++) {
                const int col = wc * 64 + nt * 8 + (lane & 3) * 2;
                float2 b = *(const float2*)&b_out[col];
                *(float2*)&out[(size_t)node * 128 + col] =
                    make_float2(acc[nt][h * 2] + b.x, acc[nt][h * 2 + 1] + b.y);
            }
        }
    }
}

// ---------------------------------------------------------------------------
// node-level FFMA body: 16 nodes per block-slot, 256 threads
// ---------------------------------------------------------------------------
__device__ __forceinline__ void nodes_body(int base, int s, int e,
                                           const int* __restrict__ x,
                                           const int* __restrict__ mask,
                                           const int* __restrict__ children,
                                           const float* __restrict__ U,
                                           float (*agg)[128])
{
    const int tid = threadIdx.x;
    const int col = tid & 127, half = tid >> 7;

#pragma unroll
    for (int g = 0; g < 8; g++) {
        const int node = base + half * 8 + g;
        const int nb = (node < e) ? node : s;
        float sum = 0.f;
#pragma unroll
        for (int c = 0; c < 8; c++)
            sum += g_h[(size_t)children[(size_t)nb * 8 + c] * 128 + col];
        agg[half * 8 + g][col] = sum;
    }
    __syncthreads();

    float acc[8];
#pragma unroll
    for (int g = 0; g < 8; g++) acc[g] = 0.f;
#pragma unroll 4
    for (int k = 0; k < 128; k++) {
        const float u = __ldg(&U[k * 128 + col]);
#pragma unroll
        for (int g = 0; g < 8; g++)
            acc[g] = fmaf(agg[half * 8 + g][k], u, acc[g]);
    }

#pragma unroll
    for (int g = 0; g < 8; g++) {
        const int node = base + half * 8 + g;
        if (node < e) {
            const float mf = (float)mask[node];
            const int xm = x[node] * mask[node];
            const float hin = g_Pb[(size_t)xm * 128 + col] * mf;
            g_h[(size_t)node * 128 + col] = tanhf(hin + acc[g]);
        }
    }
}

__global__ void __launch_bounds__(256, 4)
k_nodes(int s, int n, const int* __restrict__ x, const int* __restrict__ mask,
        const int* __restrict__ children, const float* __restrict__ U)
{
    __shared__ float agg[16][128];
    nodes_body(s + blockIdx.x * 16, s, s + n, x, mask, children, U, agg);
}

__global__ void __launch_bounds__(256, 1)
k_tail(const int* __restrict__ x, const int* __restrict__ mask,
       const int* __restrict__ children, const float* __restrict__ U)
{
    __shared__ float agg[16][128];
    const int ls[3] = {9, 1, 0};
    const int ln[3] = {64, 8, 1};
    for (int lv = 0; lv < 3; lv++) {
        const int s = ls[lv], e = s + ln[lv];
        for (int base = s; base < e; base += 16) {
            nodes_body(base, s, e, x, mask, children, U, agg);
            __syncthreads();
        }
    }
}

// ---------------------------------------------------------------------------
// k_out_leaf: out[leaf] = mask * Q[x] + b_out
// ---------------------------------------------------------------------------
__global__ void __launch_bounds__(256)
k_out_leaf(const int* __restrict__ x, const int* __restrict__ mask,
           const float* __restrict__ b_out, float* __restrict__ out)
{
    const float4 bv = ((const float4*)b_out)[threadIdx.x & 31];
    int idx = blockIdx.x * 256 + threadIdx.x;
#pragma unroll
    for (int it = 0; it < 4; it++, idx += 8192 * 256) {
        const int rr = idx >> 5, c = idx & 31;
        const int node = NINT + rr;
        const int m = mask[node];
        const int xm = x[node] * m;
        const float mf = (float)m;
        float4 q = ((const float4*)g_Q)[(size_t)xm * 32 + c];
        float4 o = make_float4(fmaf(q.x, mf, bv.x), fmaf(q.y, mf, bv.y),
                               fmaf(q.z, mf, bv.z), fmaf(q.w, mf, bv.w));
        ((float4*)out)[(size_t)node * 32 + c] = o;
    }
}

// ---------------------------------------------------------------------------
extern "C" void kernel_launch(void* const* d_in, const int* in_sizes, int n_in,
                              void* d_out, int out_size)
{
    const int*   x        = (const int*)  d_in[0];
    const int*   mask     = (const int*)  d_in[1];
    const int*   children = (const int*)  d_in[2];
    const float* emb      = (const float*)d_in[3];
    const float* W_in     = (const float*)d_in[4];
    const float* b_in     = (const float*)d_in[5];
    const float* U        = (const float*)d_in[6];
    const float* W_out    = (const float*)d_in[7];
    const float* b_out    = (const float*)d_in[8];
    float*       out      = (float*)d_out;
    (void)in_sizes; (void)n_in; (void)out_size;

    static cudaStream_t sA = nullptr, sB = nullptr;
    static cudaEvent_t  eT, eH5, eJ1, eJ2;
    if (!sA) {
        cudaStreamCreateWithFlags(&sA, cudaStreamNonBlocking);
        cudaStreamCreateWithFlags(&sB, cudaStreamNonBlocking);
        cudaEventCreateWithFlags(&eT,  cudaEventDisableTiming);
        cudaEventCreateWithFlags(&eH5, cudaEventDisableTiming);
        cudaEventCreateWithFlags(&eJ1, cudaEventDisableTiming);
        cudaEventCreateWithFlags(&eJ2, cudaEventDisableTiming);
    }
    cudaStream_t s0 = 0;

    k_prep<<<48, 256, 0, s0>>>(W_in, U, W_out);
    // Pb, T  (critical path)
    k_vocab1<<<500, 256, SMEM_BYTES, s0>>>(emb, b_in);
    cudaEventRecord(eT, s0);

    // side stream A: Q = T@W_out, then leaf outputs
    cudaStreamWaitEvent(sA, eT, 0);
    k_vocab2<<<500, 256, SMEM_BYTES, sA>>>();
    k_out_leaf<<<8192, 256, 0, sA>>>(x, mask, b_out, out);
    cudaEventRecord(eJ1, sA);

    // critical path: level 5 hidden
    k_level5<<<512, 256, SMEM_BYTES, s0>>>(4681, x, mask, children);
    cudaEventRecord(eH5, s0);

    // side stream B: output GEMM for L5 rows
    cudaStreamWaitEvent(sB, eH5, 0);
    k_out_t<<<512, 256, SMEM_BYTES, sB>>>(4681, 32768, b_out, out);
    cudaEventRecord(eJ2, sB);

    // critical path: L4..L0, then output head
    k_nodes<<<256, 256, 0, s0>>>(585, 4096, x, mask, children, U); // L4
    k_nodes<<< 32, 256, 0, s0>>>( 73,  512, x, mask, children, U); // L3
    k_tail <<<  1, 256, 0, s0>>>(x, mask, children, U);            // L2..L0
    k_out_t<<<74, 256, SMEM_BYTES, s0>>>(0, 4681, b_out, out);     // out rows 0..4681

    cudaStreamWaitEvent(s0, eJ1, 0);
    cudaStreamWaitEvent(s0, eJ2, 0);
}